// round 15
// baseline (speedup 1.0000x reference)
#include <cuda_runtime.h>
#include <cuda_fp16.h>
#include <cstdint>
#include <math.h>

#define NL 6
#define NH 16
#define E  1024
#define V  50257
#define B  4
#define T  1024
#define BT (B*T)
#define HD 64
#define NCB (((V + 127) / 128) * 2)   // 786 64-col LSE chunks per row

// ---------------- scratch ---------------------------------------------------
__device__ float  g_x[BT * E];             // residual stream (fp32)
__device__ float  g_nll[BT];
__device__ float  g_lse_m[BT * NCB];       // partial row max per 64-col chunk
__device__ float  g_lse_l[BT * NCB];       // partial row sum-exp per chunk
__device__ __half g_a16[BT * E];           // fp16 activations (LN out / attn out)
__device__ __half g_m16[BT * 4 * E];       // fp16 MLP hidden (GELU out)
__device__ __half g_q16[BT * 3 * E];       // fp16 qkv (gemm out, feeds attention)
// fp16 weights (converted once per launch)
__device__ __half g_w_qkv[NL * 3 * E * E];
__device__ __half g_w_proj[NL * E * E];
__device__ __half g_w_fc[NL * 4 * E * E];
__device__ __half g_w_fcp[NL * 4 * E * E];
__device__ __half g_w_lm[(size_t)V * E];

// ---------------- fp32 -> fp16 conversion (all weights, one launch) ---------
struct CvtArgs {
    const float* s[5];
    __half*      d[5];
    long         n[5];
};

__global__ void cvt_all_kernel(CvtArgs a)
{
    int z = blockIdx.z;
    const float* s = a.s[z];
    __half* d = a.d[z];
    long n = a.n[z];
    long i = (long)blockIdx.x * blockDim.x + threadIdx.x;
    long stride = (long)gridDim.x * blockDim.x;
    for (long j = i * 4; j < n; j += stride * 4) {
        float4 v = *(const float4*)(s + j);
        *(__half2*)(d + j)     = __floats2half2_rn(v.x, v.y);
        *(__half2*)(d + j + 2) = __floats2half2_rn(v.z, v.w);
    }
}

// ---------------- embedding -------------------------------------------------
__global__ void embed_kernel(const int* __restrict__ idx,
                             const float* __restrict__ wte,
                             const float* __restrict__ wpe,
                             float* __restrict__ out)
{
    int row = blockIdx.x;
    int t = row % T;
    int tok = idx[row];
    const float* we = wte + (size_t)tok * E;
    const float* wp = wpe + (size_t)t * E;
    float* o = out + (size_t)row * E;
    for (int i = threadIdx.x; i < E; i += blockDim.x)
        o[i] = we[i] + wp[i];
}

// ---------------- layernorm (fp32 in, fp16 out) -----------------------------
__global__ void ln_kernel(const float* __restrict__ x,
                          const float* __restrict__ w,
                          const float* __restrict__ b,
                          __half* __restrict__ out)
{
    int row = blockIdx.x;
    int tid = threadIdx.x;
    const float* xr = x + (size_t)row * E;
    float s = 0.f, ss = 0.f;
    for (int i = tid; i < E; i += blockDim.x) {
        float v = xr[i];
        s += v; ss += v * v;
    }
    __shared__ float rs[32], rss[32];
    #pragma unroll
    for (int o = 16; o > 0; o >>= 1) {
        s  += __shfl_xor_sync(0xffffffffu, s, o);
        ss += __shfl_xor_sync(0xffffffffu, ss, o);
    }
    int wid = tid >> 5, lid = tid & 31;
    if (lid == 0) { rs[wid] = s; rss[wid] = ss; }
    __syncthreads();
    if (tid < 32) {
        int nw = blockDim.x >> 5;
        float a = (tid < nw) ? rs[tid] : 0.f;
        float c = (tid < nw) ? rss[tid] : 0.f;
        #pragma unroll
        for (int o = 16; o > 0; o >>= 1) {
            a += __shfl_xor_sync(0xffffffffu, a, o);
            c += __shfl_xor_sync(0xffffffffu, c, o);
        }
        if (tid == 0) { rs[0] = a; rss[0] = c; }
    }
    __syncthreads();
    float mu  = rs[0] * (1.0f / E);
    float var = rss[0] * (1.0f / E) - mu * mu;
    float r = rsqrtf(var + 1e-5f);
    __half* orow = out + (size_t)row * E;
    for (int i = tid; i < E; i += blockDim.x)
        orow[i] = __float2half((xr[i] - mu) * r * w[i] + b[i]);
}

// ---------------- fp16 tensor-core GEMM (128x128, BK=64, 3 stages, occ 2) ----
#define BM 128
#define BN 128
#define BKH 64
#define STG 3
#define ROWB 144                     // 128B data + 16B pad: LDSM conflict-free
#define STAGE_B (BM * ROWB)          // 18432 B
#define GSMEM (2 * STG * STAGE_B)    // 110592 B

#define LDSM4(r, a) \
    asm volatile("ldmatrix.sync.aligned.m8n8.x4.shared.b16 {%0,%1,%2,%3}, [%4];" \
        : "=r"((r)[0]), "=r"((r)[1]), "=r"((r)[2]), "=r"((r)[3]) : "r"(a))

#define LDSM4T(r, a) \
    asm volatile("ldmatrix.sync.aligned.m8n8.x4.trans.shared.b16 {%0,%1,%2,%3}, [%4];" \
        : "=r"((r)[0]), "=r"((r)[1]), "=r"((r)[2]), "=r"((r)[3]) : "r"(a))

#define MMA16816(c, a, b0, b1) \
    asm volatile("mma.sync.aligned.m16n8k16.row.col.f32.f16.f16.f32 " \
        "{%0,%1,%2,%3}, {%4,%5,%6,%7}, {%8,%9}, {%0,%1,%2,%3};" \
        : "+f"((c)[0]), "+f"((c)[1]), "+f"((c)[2]), "+f"((c)[3]) \
        : "r"((a)[0]), "r"((a)[1]), "r"((a)[2]), "r"((a)[3]), "r"(b0), "r"(b1))

__device__ __forceinline__ uint32_t smem_u32(const void* p) {
    uint32_t a;
    asm("{ .reg .u64 t; cvta.to.shared.u64 t, %1; cvt.u32.u64 %0, t; }" : "=r"(a) : "l"(p));
    return a;
}

__global__ void __launch_bounds__(256, 2)
gemm_h(const __half* __restrict__ A, const __half* __restrict__ Bw,
       float* __restrict__ Cf, __half* __restrict__ Ch,
       const float* __restrict__ Res, int N, int K, int act_gelu,
       float* __restrict__ lseM, float* __restrict__ lseL)
{
    extern __shared__ char sm[];
    uint32_t sA = smem_u32(sm);
    uint32_t sB = sA + STG * STAGE_B;

    int tid = threadIdx.x;
    int warp = tid >> 5, lane = tid & 31;
    int wm = warp & 3, wn = warp >> 2;
    int lrow = lane & 7, lsel = lane >> 3;
    int gq = lane >> 2, tg = lane & 3;
    int row0 = blockIdx.x * BM, col0 = blockIdx.y * BN;
    int ktiles = K / BKH;

    float acc[2][8][4];
    #pragma unroll
    for (int mi = 0; mi < 2; mi++)
        #pragma unroll
        for (int ni = 0; ni < 8; ni++)
            #pragma unroll
            for (int r = 0; r < 4; r++) acc[mi][ni][r] = 0.f;

#define ISSUE(st, kt) do { \
    size_t kofs = (size_t)(kt) * BKH; \
    _Pragma("unroll") \
    for (int ii = 0; ii < 4; ii++) { \
        int idx = tid + 256 * ii; int r = idx >> 3; int c = idx & 7; \
        uint32_t da = sA + (st) * STAGE_B + r * ROWB + c * 16; \
        const __half* ga = A + (size_t)(row0 + r) * K + kofs + c * 8; \
        asm volatile("cp.async.cg.shared.global [%0], [%1], 16;" :: "r"(da), "l"(ga)); \
    } \
    _Pragma("unroll") \
    for (int ii = 0; ii < 4; ii++) { \
        int idx = tid + 256 * ii; int r = idx >> 3; int c = idx & 7; \
        int brow = col0 + r; \
        int sz = (brow < N) ? 16 : 0; \
        const __half* gb = Bw + (size_t)(brow < N ? brow : 0) * K + kofs + c * 8; \
        uint32_t db = sB + (st) * STAGE_B + r * ROWB + c * 16; \
        asm volatile("cp.async.cg.shared.global [%0], [%1], 16, %2;" :: "r"(db), "l"(gb), "r"(sz)); \
    } \
} while (0)

    ISSUE(0, 0); asm volatile("cp.async.commit_group;" ::: "memory");
    ISSUE(1, 1); asm volatile("cp.async.commit_group;" ::: "memory");

    for (int kt = 0; kt < ktiles; kt++) {
        asm volatile("cp.async.wait_group 1;" ::: "memory");
        __syncthreads();
        int nk = kt + STG - 1;
        if (nk < ktiles) {
            int st = nk % STG;
            ISSUE(st, nk);
        }
        asm volatile("cp.async.commit_group;" ::: "memory");

        int buf = kt % STG;
        uint32_t aw = sA + buf * STAGE_B
                    + (wm * 32 + (lsel & 1) * 8 + lrow) * ROWB + (lsel >> 1) * 16;
        uint32_t bw = sB + buf * STAGE_B
                    + (wn * 64 + (lsel >> 1) * 8 + lrow) * ROWB + (lsel & 1) * 16;

        // fragment double buffering: prefetch next ks's B frags during MMAs
        uint32_t bfr[2][4][4];
        #pragma unroll
        for (int nj = 0; nj < 4; nj++)
            LDSM4(bfr[0][nj], bw + nj * 16 * ROWB);

        #pragma unroll
        for (int ks = 0; ks < 4; ks++) {
            int cb = ks & 1;
            uint32_t a0[4], a1[4];
            LDSM4(a0, aw + ks * 32);
            LDSM4(a1, aw + 16 * ROWB + ks * 32);
            if (ks < 3) {
                #pragma unroll
                for (int nj = 0; nj < 4; nj++)
                    LDSM4(bfr[cb ^ 1][nj], bw + nj * 16 * ROWB + (ks + 1) * 32);
            }
            #pragma unroll
            for (int nj = 0; nj < 4; nj++) {
                MMA16816(acc[0][nj * 2],     a0, bfr[cb][nj][0], bfr[cb][nj][1]);
                MMA16816(acc[0][nj * 2 + 1], a0, bfr[cb][nj][2], bfr[cb][nj][3]);
                MMA16816(acc[1][nj * 2],     a1, bfr[cb][nj][0], bfr[cb][nj][1]);
                MMA16816(acc[1][nj * 2 + 1], a1, bfr[cb][nj][2], bfr[cb][nj][3]);
            }
        }
    }

    // epilogue (alignment-safe for odd N)
    #pragma unroll
    for (int mi = 0; mi < 2; mi++) {
        #pragma unroll
        for (int ni = 0; ni < 8; ni++) {
            int row = row0 + wm * 32 + mi * 16 + gq;
            int col = col0 + wn * 64 + ni * 8 + tg * 2;
            #pragma unroll
            for (int h = 0; h < 2; h++) {
                int rr = row + h * 8;
                float v0 = acc[mi][ni][h * 2], v1 = acc[mi][ni][h * 2 + 1];
                size_t off = (size_t)rr * N + col;
                bool ok0 = col < N, ok1 = col + 1 < N;
                if (Res) {
                    if (ok0) v0 += Res[off];
                    if (ok1) v1 += Res[off + 1];
                }
                if (act_gelu) {
                    v0 = 0.5f * v0 * (1.0f + erff(v0 * 0.70710678118654752f));
                    v1 = 0.5f * v1 * (1.0f + erff(v1 * 0.70710678118654752f));
                }
                if (Ch) {
                    if (ok1) *(__half2*)(Ch + off) = __floats2half2_rn(v0, v1);
                    else if (ok0) Ch[off] = __float2half(v0);
                } else {
                    if (ok1 && ((off & 1) == 0)) {
                        *(float2*)(Cf + off) = make_float2(v0, v1);
                    } else {
                        if (ok0) Cf[off] = v0;
                        if (ok1) Cf[off + 1] = v1;
                    }
                }
            }
        }
    }

    // fused partial LSE (lm_head only). One (m,l) per (row, 64-col chunk).
    if (lseM) {
        int chunk = blockIdx.y * 2 + wn;
        #pragma unroll
        for (int mi = 0; mi < 2; mi++) {
            #pragma unroll
            for (int h = 0; h < 2; h++) {
                int rr = row0 + wm * 32 + mi * 16 + gq + h * 8;
                float lm = -INFINITY;
                #pragma unroll
                for (int ni = 0; ni < 8; ni++) {
                    int col = col0 + wn * 64 + ni * 8 + tg * 2;
                    float v0 = (col     < N) ? acc[mi][ni][h * 2]     : -INFINITY;
                    float v1 = (col + 1 < N) ? acc[mi][ni][h * 2 + 1] : -INFINITY;
                    lm = fmaxf(lm, fmaxf(v0, v1));
                }
                lm = fmaxf(lm, __shfl_xor_sync(0xffffffffu, lm, 1));
                lm = fmaxf(lm, __shfl_xor_sync(0xffffffffu, lm, 2));
                float ll = 0.f;
                #pragma unroll
                for (int ni = 0; ni < 8; ni++) {
                    int col = col0 + wn * 64 + ni * 8 + tg * 2;
                    if (col     < N) ll += __expf(acc[mi][ni][h * 2]     - lm);
                    if (col + 1 < N) ll += __expf(acc[mi][ni][h * 2 + 1] - lm);
                }
                ll += __shfl_xor_sync(0xffffffffu, ll, 1);
                ll += __shfl_xor_sync(0xffffffffu, ll, 2);
                if (tg == 0) {
                    lseM[(size_t)rr * NCB + chunk] = lm;
                    lseL[(size_t)rr * NCB + chunk] = ll;
                }
            }
        }
    }
}

// ---------------- tensor-core flash attention (fp16 mma, fp32 softmax) ------
#define AQT 64
#define AST 72           // smem row stride in halves (64 + 8 pad)

__global__ void __launch_bounds__(128)
attn_kernel(const __half* __restrict__ qkv, __half* __restrict__ y)
{
    __shared__ __half Qs[AQT * AST];
    __shared__ __half Ks[AQT * AST];
    __shared__ __half Vs[AQT * AST];

    int qt = blockIdx.x, h = blockIdx.y, b = blockIdx.z;
    int tid = threadIdx.x;
    int w = tid >> 5, lane = tid & 31;
    int lrow = lane & 7, lsel = lane >> 3;
    int g = lane >> 2, tg = lane & 3;
    int E3 = 3 * E;
    int q0 = qt * AQT;

    uint32_t sQ = smem_u32(Qs), sK = smem_u32(Ks), sV = smem_u32(Vs);

    for (int it = 0; it < 4; it++) {
        int idx = tid + 128 * it;
        int r = idx >> 3, seg = idx & 7;
        const uint4* src = (const uint4*)(qkv + (size_t)(b * T + q0 + r) * E3 + h * HD) + seg;
        *(uint4*)(Qs + r * AST + seg * 8) = *src;
    }
    __syncthreads();

    uint32_t qa[4][4];
    {
        uint32_t qaddr = sQ + (uint32_t)((16 * w + (lsel & 1) * 8 + lrow) * AST) * 2
                       + (uint32_t)((lsel >> 1) * 8) * 2;
        #pragma unroll
        for (int kk = 0; kk < 4; kk++)
            LDSM4(qa[kk], qaddr + kk * 32);
    }

    float oacc[8][4];
    #pragma unroll
    for (int nj = 0; nj < 8; nj++)
        #pragma unroll
        for (int r = 0; r < 4; r++) oacc[nj][r] = 0.f;
    float m0 = -INFINITY, m1 = -INFINITY, l0 = 0.f, l1 = 0.f;

    for (int k0 = 0; k0 <= q0; k0 += AQT) {
        __syncthreads();
        for (int it = 0; it < 4; it++) {
            int idx = tid + 128 * it;
            int r = idx >> 3, seg = idx & 7;
            const __half* base = qkv + (size_t)(b * T + k0 + r) * E3 + E + h * HD;
            *(uint4*)(Ks + r * AST + seg * 8) = *((const uint4*)base + seg);
            *(uint4*)(Vs + r * AST + seg * 8) = *((const uint4*)(base + E) + seg);
        }
        __syncthreads();

        float sacc[8][4];
        #pragma unroll
        for (int nj = 0; nj < 8; nj++)
            #pragma unroll
            for (int r = 0; r < 4; r++) sacc[nj][r] = 0.f;

        uint32_t kbase = sK + (uint32_t)(((lsel >> 1) * 8 + lrow) * AST) * 2
                       + (uint32_t)((lsel & 1) * 8) * 2;
        #pragma unroll
        for (int njp = 0; njp < 4; njp++) {
            #pragma unroll
            for (int kk = 0; kk < 4; kk++) {
                uint32_t kb[4];
                LDSM4(kb, kbase + (uint32_t)(16 * njp * AST) * 2 + kk * 32);
                MMA16816(sacc[2 * njp],     qa[kk], kb[0], kb[1]);
                MMA16816(sacc[2 * njp + 1], qa[kk], kb[2], kb[3]);
            }
        }

        #pragma unroll
        for (int nj = 0; nj < 8; nj++)
            #pragma unroll
            for (int r = 0; r < 4; r++) sacc[nj][r] *= 0.125f;
        if (k0 == q0) {
            int qr0 = 16 * w + g, qr1 = qr0 + 8;
            #pragma unroll
            for (int nj = 0; nj < 8; nj++) {
                int kc = 8 * nj + 2 * tg;
                if (kc     > qr0) sacc[nj][0] = -INFINITY;
                if (kc + 1 > qr0) sacc[nj][1] = -INFINITY;
                if (kc     > qr1) sacc[nj][2] = -INFINITY;
                if (kc + 1 > qr1) sacc[nj][3] = -INFINITY;
            }
        }

        float rm0 = -INFINITY, rm1 = -INFINITY;
        #pragma unroll
        for (int nj = 0; nj < 8; nj++) {
            rm0 = fmaxf(rm0, fmaxf(sacc[nj][0], sacc[nj][1]));
            rm1 = fmaxf(rm1, fmaxf(sacc[nj][2], sacc[nj][3]));
        }
        rm0 = fmaxf(rm0, __shfl_xor_sync(0xffffffffu, rm0, 1));
        rm0 = fmaxf(rm0, __shfl_xor_sync(0xffffffffu, rm0, 2));
        rm1 = fmaxf(rm1, __shfl_xor_sync(0xffffffffu, rm1, 1));
        rm1 = fmaxf(rm1, __shfl_xor_sync(0xffffffffu, rm1, 2));

        float nm0 = fmaxf(m0, rm0), nm1 = fmaxf(m1, rm1);
        float corr0 = __expf(m0 - nm0), corr1 = __expf(m1 - nm1);
        m0 = nm0; m1 = nm1;

        float p[8][4];
        float ls0 = 0.f, ls1 = 0.f;
        #pragma unroll
        for (int nj = 0; nj < 8; nj++) {
            p[nj][0] = __expf(sacc[nj][0] - nm0);
            p[nj][1] = __expf(sacc[nj][1] - nm0);
            p[nj][2] = __expf(sacc[nj][2] - nm1);
            p[nj][3] = __expf(sacc[nj][3] - nm1);
            ls0 += p[nj][0] + p[nj][1];
            ls1 += p[nj][2] + p[nj][3];
        }
        ls0 += __shfl_xor_sync(0xffffffffu, ls0, 1);
        ls0 += __shfl_xor_sync(0xffffffffu, ls0, 2);
        ls1 += __shfl_xor_sync(0xffffffffu, ls1, 1);
        ls1 += __shfl_xor_sync(0xffffffffu, ls1, 2);
        l0 = l0 * corr0 + ls0;
        l1 = l1 * corr1 + ls1;

        #pragma unroll
        for (int nj = 0; nj < 8; nj++) {
            oacc[nj][0] *= corr0; oacc[nj][1] *= corr0;
            oacc[nj][2] *= corr1; oacc[nj][3] *= corr1;
        }

        uint32_t pa[4][4];
        #pragma unroll
        for (int kk = 0; kk < 4; kk++) {
            __half2 h0 = __floats2half2_rn(p[2 * kk][0],     p[2 * kk][1]);
            __half2 h1 = __floats2half2_rn(p[2 * kk][2],     p[2 * kk][3]);
            __half2 h2 = __floats2half2_rn(p[2 * kk + 1][0], p[2 * kk + 1][1]);
            __half2 h3 = __floats2half2_rn(p[2 * kk + 1][2], p[2 * kk + 1][3]);
            pa[kk][0] = *(uint32_t*)&h0;
            pa[kk][1] = *(uint32_t*)&h1;
            pa[kk][2] = *(uint32_t*)&h2;
            pa[kk][3] = *(uint32_t*)&h3;
        }

        uint32_t vbase = sV + (uint32_t)(((lsel & 1) * 8 + lrow) * AST) * 2
                       + (uint32_t)((lsel >> 1) * 8) * 2;
        #pragma unroll
        for (int njp = 0; njp < 4; njp++) {
            #pragma unroll
            for (int kk = 0; kk < 4; kk++) {
                uint32_t vb[4];
                LDSM4T(vb, vbase + (uint32_t)(16 * kk * AST) * 2 + (uint32_t)(16 * njp) * 2);
                MMA16816(oacc[2 * njp],     pa[kk], vb[0], vb[1]);
                MMA16816(oacc[2 * njp + 1], pa[kk], vb[2], vb[3]);
            }
        }
    }

    float inv0 = 1.f / l0, inv1 = 1.f / l1;
    int row0g = b * T + q0 + 16 * w + g;
    #pragma unroll
    for (int nj = 0; nj < 8; nj++) {
        int col = h * HD + 8 * nj + 2 * tg;
        __half2 v0 = __floats2half2_rn(oacc[nj][0] * inv0, oacc[nj][1] * inv0);
        __half2 v1 = __floats2half2_rn(oacc[nj][2] * inv1, oacc[nj][3] * inv1);
        *(__half2*)(y + (size_t)row0g * E + col) = v0;
        *(__half2*)(y + (size_t)(row0g + 8) * E + col) = v1;
    }
}

// ---------------- loss merge (reads partial LSE pairs, not logits) -----------
__global__ void loss_merge_kernel(const float* __restrict__ logits,
                                  const int* __restrict__ tgt)
{
    int row = blockIdx.x;
    int tid = threadIdx.x;
    const float* pm = g_lse_m + (size_t)row * NCB;
    const float* pl = g_lse_l + (size_t)row * NCB;
    __shared__ float rmx[8], rsm[8];

    float m = -INFINITY, l = 0.f;
    for (int i = tid; i < NCB; i += 256) {
        float mi = pm[i], li = pl[i];
        float nm = fmaxf(m, mi);
        l = l * __expf(m - nm) + li * __expf(mi - nm);
        m = nm;
    }
    #pragma unroll
    for (int o = 16; o > 0; o >>= 1) {
        float om = __shfl_xor_sync(0xffffffffu, m, o);
        float ol = __shfl_xor_sync(0xffffffffu, l, o);
        float nm = fmaxf(m, om);
        l = l * __expf(m - nm) + ol * __expf(om - nm);
        m = nm;
    }
    if ((tid & 31) == 0) { rmx[tid >> 5] = m; rsm[tid >> 5] = l; }
    __syncthreads();
    if (tid == 0) {
        float tm = rmx[0], ts = rsm[0];
        #pragma unroll
        for (int w = 1; w < 8; w++) {
            float nm = fmaxf(tm, rmx[w]);
            ts = ts * __expf(tm - nm) + rsm[w] * __expf(rmx[w] - nm);
            tm = nm;
        }
        float lse = tm + logf(ts);
        int tg = tgt[row];
        g_nll[row] = (tg != -1) ? (lse - logits[(size_t)row * V + tg]) : 0.f;
    }
}

__global__ void loss_final_kernel(const int* __restrict__ tgt,
                                  float* __restrict__ out_loss)
{
    int tid = threadIdx.x;
    float s = 0.f;
    int c = 0;
    for (int i = tid; i < BT; i += blockDim.x) {
        s += g_nll[i];
        if (tgt[i] != -1) c++;
    }
    __shared__ float sf[32];
    __shared__ int si[32];
    #pragma unroll
    for (int o = 16; o > 0; o >>= 1) {
        s += __shfl_xor_sync(0xffffffffu, s, o);
        c += __shfl_xor_sync(0xffffffffu, c, o);
    }
    if ((tid & 31) == 0) { sf[tid >> 5] = s; si[tid >> 5] = c; }
    __syncthreads();
    if (tid == 0) {
        int nw = blockDim.x >> 5;
        float ts = 0.f; int tc = 0;
        for (int w = 0; w < nw; w++) { ts += sf[w]; tc += si[w]; }
        out_loss[0] = ts / fmaxf((float)tc, 1.f);
    }
}

// ---------------- launch ----------------------------------------------------
extern "C" void kernel_launch(void* const* d_in, const int* in_sizes, int n_in,
                              void* d_out, int out_size)
{
    const int*   idx         = (const int*)d_in[0];
    const int*   targets     = (const int*)d_in[1];
    const float* wte         = (const float*)d_in[2];
    const float* wpe         = (const float*)d_in[3];
    const float* ln1_w       = (const float*)d_in[4];
    const float* ln1_b       = (const float*)d_in[5];
    const float* attn_w      = (const float*)d_in[6];
    const float* attn_proj_w = (const float*)d_in[7];
    const float* ln2_w       = (const float*)d_in[8];
    const float* ln2_b       = (const float*)d_in[9];
    const float* fc_w        = (const float*)d_in[10];
    const float* fc_proj_w   = (const float*)d_in[11];
    const float* lnf_w       = (const float*)d_in[12];
    const float* lnf_b       = (const float*)d_in[13];
    const float* lm_w        = (const float*)d_in[14];
    float* out = (float*)d_out;

    cudaFuncSetAttribute(gemm_h, cudaFuncAttributeMaxDynamicSharedMemorySize, GSMEM);

    float *gx, *glm, *gll;
    __half *ga16, *gm16, *gq16, *wqkv, *wproj, *wfc, *wfcp, *wlm;
    cudaGetSymbolAddress((void**)&gx,    g_x);
    cudaGetSymbolAddress((void**)&glm,   g_lse_m);
    cudaGetSymbolAddress((void**)&gll,   g_lse_l);
    cudaGetSymbolAddress((void**)&ga16,  g_a16);
    cudaGetSymbolAddress((void**)&gm16,  g_m16);
    cudaGetSymbolAddress((void**)&gq16,  g_q16);
    cudaGetSymbolAddress((void**)&wqkv,  g_w_qkv);
    cudaGetSymbolAddress((void**)&wproj, g_w_proj);
    cudaGetSymbolAddress((void**)&wfc,   g_w_fc);
    cudaGetSymbolAddress((void**)&wfcp,  g_w_fcp);
    cudaGetSymbolAddress((void**)&wlm,   g_w_lm);

    CvtArgs ca;
    ca.s[0] = attn_w;      ca.d[0] = wqkv;  ca.n[0] = (long)NL * 3 * E * E;
    ca.s[1] = attn_proj_w; ca.d[1] = wproj; ca.n[1] = (long)NL * E * E;
    ca.s[2] = fc_w;        ca.d[2] = wfc;   ca.n[2] = (long)NL * 4 * E * E;
    ca.s[3] = fc_proj_w;   ca.d[3] = wfcp;  ca.n[3] = (long)NL * 4 * E * E;
    ca.s[4] = lm_w;        ca.d[4] = wlm;   ca.n[4] = (long)V * E;
    cvt_all_kernel<<<dim3(256, 1, 5), 256>>>(ca);

    embed_kernel<<<BT, 256>>>(idx, wte, wpe, gx);

    for (int i = 0; i < NL; i++) {
        ln_kernel<<<BT, 256>>>(gx, ln1_w + (size_t)i * E, ln1_b + (size_t)i * E, ga16);
        gemm_h<<<dim3(BT / BM, 3 * E / BN), 256, GSMEM>>>(
            ga16, wqkv + (size_t)i * 3 * E * E, nullptr, gq16, nullptr, 3 * E, E, 0,
            nullptr, nullptr);
        attn_kernel<<<dim3(T / AQT, NH, B), 128>>>(gq16, ga16);
        gemm_h<<<dim3(BT / BM, E / BN), 256, GSMEM>>>(
            ga16, wproj + (size_t)i * E * E, gx, nullptr, gx, E, E, 0,
            nullptr, nullptr);
        ln_kernel<<<BT, 256>>>(gx, ln2_w + (size_t)i * E, ln2_b + (size_t)i * E, ga16);
        gemm_h<<<dim3(BT / BM, 4 * E / BN), 256, GSMEM>>>(
            ga16, wfc + (size_t)i * 4 * E * E, nullptr, gm16, nullptr, 4 * E, E, 1,
            nullptr, nullptr);
        gemm_h<<<dim3(BT / BM, E / BN), 256, GSMEM>>>(
            gm16, wfcp + (size_t)i * 4 * E * E, gx, nullptr, gx, E, 4 * E, 0,
            nullptr, nullptr);
    }

    ln_kernel<<<BT, 256>>>(gx, lnf_w, lnf_b, ga16);
    gemm_h<<<dim3(BT / BM, (V + BN - 1) / BN), 256, GSMEM>>>(
        ga16, wlm, out, nullptr, nullptr, V, E, 0, glm, gll);

    long long btv = (long long)BT * V;
    if ((long long)out_size > btv) {
        loss_merge_kernel<<<BT, 256>>>(out, targets);
        loss_final_kernel<<<1, 1024>>>(targets, out + btv);
    }
}

// round 16
// speedup vs baseline: 1.0425x; 1.0425x over previous
#include <cuda_runtime.h>
#include <cuda_fp16.h>
#include <cstdint>
#include <math.h>

#define NL 6
#define NH 16
#define E  1024
#define V  50257
#define B  4
#define T  1024
#define BT (B*T)
#define HD 64
#define NCB (((V + 127) / 128) * 2)   // 786 64-col LSE chunks per row

// ---------------- scratch ---------------------------------------------------
__device__ float  g_x[BT * E];             // residual stream (fp32)
__device__ float  g_nll[BT];
__device__ float  g_lse_m[BT * NCB];       // partial row max per 64-col chunk
__device__ float  g_lse_l[BT * NCB];       // partial row sum-exp per chunk
__device__ __half g_a16[BT * E];           // fp16 activations (LN out / attn out)
__device__ __half g_m16[BT * 4 * E];       // fp16 MLP hidden (GELU out)
__device__ __half g_q16[BT * 3 * E];       // fp16 qkv (gemm out, feeds attention)
// fp16 weights (converted once per launch)
__device__ __half g_w_qkv[NL * 3 * E * E];
__device__ __half g_w_proj[NL * E * E];
__device__ __half g_w_fc[NL * 4 * E * E];
__device__ __half g_w_fcp[NL * 4 * E * E];
__device__ __half g_w_lm[(size_t)V * E];

// ---------------- fp32 -> fp16 conversion (all weights, one launch) ---------
struct CvtArgs {
    const float* s[5];
    __half*      d[5];
    long         n[5];
};

__global__ void cvt_all_kernel(CvtArgs a)
{
    int z = blockIdx.z;
    const float* s = a.s[z];
    __half* d = a.d[z];
    long n = a.n[z];
    long i = (long)blockIdx.x * blockDim.x + threadIdx.x;
    long stride = (long)gridDim.x * blockDim.x;
    for (long j = i * 4; j < n; j += stride * 4) {
        float4 v = *(const float4*)(s + j);
        *(__half2*)(d + j)     = __floats2half2_rn(v.x, v.y);
        *(__half2*)(d + j + 2) = __floats2half2_rn(v.z, v.w);
    }
}

// ---------------- embedding (warp per row) -----------------------------------
__global__ void embed_kernel(const int* __restrict__ idx,
                             const float* __restrict__ wte,
                             const float* __restrict__ wpe,
                             float* __restrict__ out)
{
    int warp = (blockIdx.x * blockDim.x + threadIdx.x) >> 5;
    int lane = threadIdx.x & 31;
    if (warp >= BT) return;
    int t = warp % T;
    int tok = idx[warp];
    const float4* we = (const float4*)(wte + (size_t)tok * E);
    const float4* wp = (const float4*)(wpe + (size_t)t * E);
    float4* o = (float4*)(out + (size_t)warp * E);
    #pragma unroll
    for (int i = 0; i < E / 4 / 32; i++) {
        float4 a = we[lane + i * 32], b = wp[lane + i * 32];
        o[lane + i * 32] = make_float4(a.x + b.x, a.y + b.y, a.z + b.z, a.w + b.w);
    }
}

// ---------------- layernorm (warp per row; fp32 in, fp16 out) ----------------
__global__ void ln_kernel(const float* __restrict__ x,
                          const float* __restrict__ w,
                          const float* __restrict__ b,
                          __half* __restrict__ out)
{
    int warp = (blockIdx.x * blockDim.x + threadIdx.x) >> 5;
    int lane = threadIdx.x & 31;
    if (warp >= BT) return;
    const float4* xr = (const float4*)(x + (size_t)warp * E);

    float4 v[8];
    float s = 0.f, ss = 0.f;
    #pragma unroll
    for (int i = 0; i < 8; i++) {
        v[i] = xr[lane + i * 32];
        s  += v[i].x + v[i].y + v[i].z + v[i].w;
        ss += v[i].x * v[i].x + v[i].y * v[i].y + v[i].z * v[i].z + v[i].w * v[i].w;
    }
    #pragma unroll
    for (int o = 16; o > 0; o >>= 1) {
        s  += __shfl_xor_sync(0xffffffffu, s, o);
        ss += __shfl_xor_sync(0xffffffffu, ss, o);
    }
    float mu  = s * (1.0f / E);
    float var = ss * (1.0f / E) - mu * mu;
    float r = rsqrtf(var + 1e-5f);

    __half2* orow = (__half2*)(out + (size_t)warp * E);
    #pragma unroll
    for (int i = 0; i < 8; i++) {
        int c = (lane + i * 32) * 4;
        float4 wv = *(const float4*)(w + c);
        float4 bv = *(const float4*)(b + c);
        orow[(c >> 1)]     = __floats2half2_rn((v[i].x - mu) * r * wv.x + bv.x,
                                               (v[i].y - mu) * r * wv.y + bv.y);
        orow[(c >> 1) + 1] = __floats2half2_rn((v[i].z - mu) * r * wv.z + bv.z,
                                               (v[i].w - mu) * r * wv.w + bv.w);
    }
}

// ---------------- fp16 tensor-core GEMM (R14: 128x128, BK=64, 3 stages) ------
#define BM 128
#define BN 128
#define BKH 64
#define STG 3
#define ROWB 144                     // 128B data + 16B pad: LDSM conflict-free
#define STAGE_B (BM * ROWB)          // 18432 B
#define GSMEM (2 * STG * STAGE_B)    // 110592 B

#define LDSM4(r, a) \
    asm volatile("ldmatrix.sync.aligned.m8n8.x4.shared.b16 {%0,%1,%2,%3}, [%4];" \
        : "=r"((r)[0]), "=r"((r)[1]), "=r"((r)[2]), "=r"((r)[3]) : "r"(a))

#define LDSM4T(r, a) \
    asm volatile("ldmatrix.sync.aligned.m8n8.x4.trans.shared.b16 {%0,%1,%2,%3}, [%4];" \
        : "=r"((r)[0]), "=r"((r)[1]), "=r"((r)[2]), "=r"((r)[3]) : "r"(a))

#define MMA16816(c, a, b0, b1) \
    asm volatile("mma.sync.aligned.m16n8k16.row.col.f32.f16.f16.f32 " \
        "{%0,%1,%2,%3}, {%4,%5,%6,%7}, {%8,%9}, {%0,%1,%2,%3};" \
        : "+f"((c)[0]), "+f"((c)[1]), "+f"((c)[2]), "+f"((c)[3]) \
        : "r"((a)[0]), "r"((a)[1]), "r"((a)[2]), "r"((a)[3]), "r"(b0), "r"(b1))

__device__ __forceinline__ uint32_t smem_u32(const void* p) {
    uint32_t a;
    asm("{ .reg .u64 t; cvta.to.shared.u64 t, %1; cvt.u32.u64 %0, t; }" : "=r"(a) : "l"(p));
    return a;
}

__global__ void __launch_bounds__(256, 2)
gemm_h(const __half* __restrict__ A, const __half* __restrict__ Bw,
       float* __restrict__ Cf, __half* __restrict__ Ch,
       const float* __restrict__ Res, int N, int K, int act_gelu,
       float* __restrict__ lseM, float* __restrict__ lseL)
{
    extern __shared__ char sm[];
    uint32_t sA = smem_u32(sm);
    uint32_t sB = sA + STG * STAGE_B;

    int tid = threadIdx.x;
    int warp = tid >> 5, lane = tid & 31;
    int wm = warp & 3, wn = warp >> 2;
    int lrow = lane & 7, lsel = lane >> 3;
    int gq = lane >> 2, tg = lane & 3;
    int row0 = blockIdx.x * BM, col0 = blockIdx.y * BN;
    int ktiles = K / BKH;

    float acc[2][8][4];
    #pragma unroll
    for (int mi = 0; mi < 2; mi++)
        #pragma unroll
        for (int ni = 0; ni < 8; ni++)
            #pragma unroll
            for (int r = 0; r < 4; r++) acc[mi][ni][r] = 0.f;

#define ISSUE(st, kt) do { \
    size_t kofs = (size_t)(kt) * BKH; \
    _Pragma("unroll") \
    for (int ii = 0; ii < 4; ii++) { \
        int idx = tid + 256 * ii; int r = idx >> 3; int c = idx & 7; \
        uint32_t da = sA + (st) * STAGE_B + r * ROWB + c * 16; \
        const __half* ga = A + (size_t)(row0 + r) * K + kofs + c * 8; \
        asm volatile("cp.async.cg.shared.global [%0], [%1], 16;" :: "r"(da), "l"(ga)); \
    } \
    _Pragma("unroll") \
    for (int ii = 0; ii < 4; ii++) { \
        int idx = tid + 256 * ii; int r = idx >> 3; int c = idx & 7; \
        int brow = col0 + r; \
        int sz = (brow < N) ? 16 : 0; \
        const __half* gb = Bw + (size_t)(brow < N ? brow : 0) * K + kofs + c * 8; \
        uint32_t db = sB + (st) * STAGE_B + r * ROWB + c * 16; \
        asm volatile("cp.async.cg.shared.global [%0], [%1], 16, %2;" :: "r"(db), "l"(gb), "r"(sz)); \
    } \
} while (0)

    ISSUE(0, 0); asm volatile("cp.async.commit_group;" ::: "memory");
    ISSUE(1, 1); asm volatile("cp.async.commit_group;" ::: "memory");

    for (int kt = 0; kt < ktiles; kt++) {
        asm volatile("cp.async.wait_group 1;" ::: "memory");
        __syncthreads();
        int nk = kt + STG - 1;
        if (nk < ktiles) {
            int st = nk % STG;
            ISSUE(st, nk);
        }
        asm volatile("cp.async.commit_group;" ::: "memory");

        int buf = kt % STG;
        uint32_t aw = sA + buf * STAGE_B
                    + (wm * 32 + (lsel & 1) * 8 + lrow) * ROWB + (lsel >> 1) * 16;
        uint32_t bw = sB + buf * STAGE_B
                    + (wn * 64 + (lsel >> 1) * 8 + lrow) * ROWB + (lsel & 1) * 16;
        #pragma unroll
        for (int ks = 0; ks < 4; ks++) {
            uint32_t a0[4], a1[4];
            LDSM4(a0, aw + ks * 32);
            LDSM4(a1, aw + 16 * ROWB + ks * 32);
            #pragma unroll
            for (int nj = 0; nj < 4; nj++) {
                uint32_t b[4];
                LDSM4(b, bw + nj * 16 * ROWB + ks * 32);
                MMA16816(acc[0][nj * 2],     a0, b[0], b[1]);
                MMA16816(acc[0][nj * 2 + 1], a0, b[2], b[3]);
                MMA16816(acc[1][nj * 2],     a1, b[0], b[1]);
                MMA16816(acc[1][nj * 2 + 1], a1, b[2], b[3]);
            }
        }
    }

    // epilogue (alignment-safe for odd N)
    #pragma unroll
    for (int mi = 0; mi < 2; mi++) {
        #pragma unroll
        for (int ni = 0; ni < 8; ni++) {
            int row = row0 + wm * 32 + mi * 16 + gq;
            int col = col0 + wn * 64 + ni * 8 + tg * 2;
            #pragma unroll
            for (int h = 0; h < 2; h++) {
                int rr = row + h * 8;
                float v0 = acc[mi][ni][h * 2], v1 = acc[mi][ni][h * 2 + 1];
                size_t off = (size_t)rr * N + col;
                bool ok0 = col < N, ok1 = col + 1 < N;
                if (Res) {
                    if (ok0) v0 += Res[off];
                    if (ok1) v1 += Res[off + 1];
                }
                if (act_gelu) {
                    v0 = 0.5f * v0 * (1.0f + erff(v0 * 0.70710678118654752f));
                    v1 = 0.5f * v1 * (1.0f + erff(v1 * 0.70710678118654752f));
                }
                if (Ch) {
                    if (ok1) *(__half2*)(Ch + off) = __floats2half2_rn(v0, v1);
                    else if (ok0) Ch[off] = __float2half(v0);
                } else {
                    if (ok1 && ((off & 1) == 0)) {
                        *(float2*)(Cf + off) = make_float2(v0, v1);
                    } else {
                        if (ok0) Cf[off] = v0;
                        if (ok1) Cf[off + 1] = v1;
                    }
                }
            }
        }
    }

    // fused partial LSE (lm_head only). One (m,l) per (row, 64-col chunk).
    if (lseM) {
        int chunk = blockIdx.y * 2 + wn;
        #pragma unroll
        for (int mi = 0; mi < 2; mi++) {
            #pragma unroll
            for (int h = 0; h < 2; h++) {
                int rr = row0 + wm * 32 + mi * 16 + gq + h * 8;
                float lm = -INFINITY;
                #pragma unroll
                for (int ni = 0; ni < 8; ni++) {
                    int col = col0 + wn * 64 + ni * 8 + tg * 2;
                    float v0 = (col     < N) ? acc[mi][ni][h * 2]     : -INFINITY;
                    float v1 = (col + 1 < N) ? acc[mi][ni][h * 2 + 1] : -INFINITY;
                    lm = fmaxf(lm, fmaxf(v0, v1));
                }
                lm = fmaxf(lm, __shfl_xor_sync(0xffffffffu, lm, 1));
                lm = fmaxf(lm, __shfl_xor_sync(0xffffffffu, lm, 2));
                float ll = 0.f;
                #pragma unroll
                for (int ni = 0; ni < 8; ni++) {
                    int col = col0 + wn * 64 + ni * 8 + tg * 2;
                    if (col     < N) ll += __expf(acc[mi][ni][h * 2]     - lm);
                    if (col + 1 < N) ll += __expf(acc[mi][ni][h * 2 + 1] - lm);
                }
                ll += __shfl_xor_sync(0xffffffffu, ll, 1);
                ll += __shfl_xor_sync(0xffffffffu, ll, 2);
                if (tg == 0) {
                    lseM[(size_t)rr * NCB + chunk] = lm;
                    lseL[(size_t)rr * NCB + chunk] = ll;
                }
            }
        }
    }
}

// ---------------- tensor-core flash attention (fp16 mma, fp32 softmax) ------
#define AQT 64
#define AST 72           // smem row stride in halves (64 + 8 pad)

__global__ void __launch_bounds__(128)
attn_kernel(const __half* __restrict__ qkv, __half* __restrict__ y)
{
    __shared__ __half Qs[AQT * AST];
    __shared__ __half Ks[AQT * AST];
    __shared__ __half Vs[AQT * AST];

    int qt = blockIdx.x, h = blockIdx.y, b = blockIdx.z;
    int tid = threadIdx.x;
    int w = tid >> 5, lane = tid & 31;
    int lrow = lane & 7, lsel = lane >> 3;
    int g = lane >> 2, tg = lane & 3;
    int E3 = 3 * E;
    int q0 = qt * AQT;

    uint32_t sQ = smem_u32(Qs), sK = smem_u32(Ks), sV = smem_u32(Vs);

    for (int it = 0; it < 4; it++) {
        int idx = tid + 128 * it;
        int r = idx >> 3, seg = idx & 7;
        const uint4* src = (const uint4*)(qkv + (size_t)(b * T + q0 + r) * E3 + h * HD) + seg;
        *(uint4*)(Qs + r * AST + seg * 8) = *src;
    }
    __syncthreads();

    uint32_t qa[4][4];
    {
        uint32_t qaddr = sQ + (uint32_t)((16 * w + (lsel & 1) * 8 + lrow) * AST) * 2
                       + (uint32_t)((lsel >> 1) * 8) * 2;
        #pragma unroll
        for (int kk = 0; kk < 4; kk++)
            LDSM4(qa[kk], qaddr + kk * 32);
    }

    float oacc[8][4];
    #pragma unroll
    for (int nj = 0; nj < 8; nj++)
        #pragma unroll
        for (int r = 0; r < 4; r++) oacc[nj][r] = 0.f;
    float m0 = -INFINITY, m1 = -INFINITY, l0 = 0.f, l1 = 0.f;

    for (int k0 = 0; k0 <= q0; k0 += AQT) {
        __syncthreads();
        for (int it = 0; it < 4; it++) {
            int idx = tid + 128 * it;
            int r = idx >> 3, seg = idx & 7;
            const __half* base = qkv + (size_t)(b * T + k0 + r) * E3 + E + h * HD;
            *(uint4*)(Ks + r * AST + seg * 8) = *((const uint4*)base + seg);
            *(uint4*)(Vs + r * AST + seg * 8) = *((const uint4*)(base + E) + seg);
        }
        __syncthreads();

        float sacc[8][4];
        #pragma unroll
        for (int nj = 0; nj < 8; nj++)
            #pragma unroll
            for (int r = 0; r < 4; r++) sacc[nj][r] = 0.f;

        uint32_t kbase = sK + (uint32_t)(((lsel >> 1) * 8 + lrow) * AST) * 2
                       + (uint32_t)((lsel & 1) * 8) * 2;
        #pragma unroll
        for (int njp = 0; njp < 4; njp++) {
            #pragma unroll
            for (int kk = 0; kk < 4; kk++) {
                uint32_t kb[4];
                LDSM4(kb, kbase + (uint32_t)(16 * njp * AST) * 2 + kk * 32);
                MMA16816(sacc[2 * njp],     qa[kk], kb[0], kb[1]);
                MMA16816(sacc[2 * njp + 1], qa[kk], kb[2], kb[3]);
            }
        }

        #pragma unroll
        for (int nj = 0; nj < 8; nj++)
            #pragma unroll
            for (int r = 0; r < 4; r++) sacc[nj][r] *= 0.125f;
        if (k0 == q0) {
            int qr0 = 16 * w + g, qr1 = qr0 + 8;
            #pragma unroll
            for (int nj = 0; nj < 8; nj++) {
                int kc = 8 * nj + 2 * tg;
                if (kc     > qr0) sacc[nj][0] = -INFINITY;
                if (kc + 1 > qr0) sacc[nj][1] = -INFINITY;
                if (kc     > qr1) sacc[nj][2] = -INFINITY;
                if (kc + 1 > qr1) sacc[nj][3] = -INFINITY;
            }
        }

        float rm0 = -INFINITY, rm1 = -INFINITY;
        #pragma unroll
        for (int nj = 0; nj < 8; nj++) {
            rm0 = fmaxf(rm0, fmaxf(sacc[nj][0], sacc[nj][1]));
            rm1 = fmaxf(rm1, fmaxf(sacc[nj][2], sacc[nj][3]));
        }
        rm0 = fmaxf(rm0, __shfl_xor_sync(0xffffffffu, rm0, 1));
        rm0 = fmaxf(rm0, __shfl_xor_sync(0xffffffffu, rm0, 2));
        rm1 = fmaxf(rm1, __shfl_xor_sync(0xffffffffu, rm1, 1));
        rm1 = fmaxf(rm1, __shfl_xor_sync(0xffffffffu, rm1, 2));

        float nm0 = fmaxf(m0, rm0), nm1 = fmaxf(m1, rm1);
        float corr0 = __expf(m0 - nm0), corr1 = __expf(m1 - nm1);
        m0 = nm0; m1 = nm1;

        float p[8][4];
        float ls0 = 0.f, ls1 = 0.f;
        #pragma unroll
        for (int nj = 0; nj < 8; nj++) {
            p[nj][0] = __expf(sacc[nj][0] - nm0);
            p[nj][1] = __expf(sacc[nj][1] - nm0);
            p[nj][2] = __expf(sacc[nj][2] - nm1);
            p[nj][3] = __expf(sacc[nj][3] - nm1);
            ls0 += p[nj][0] + p[nj][1];
            ls1 += p[nj][2] + p[nj][3];
        }
        ls0 += __shfl_xor_sync(0xffffffffu, ls0, 1);
        ls0 += __shfl_xor_sync(0xffffffffu, ls0, 2);
        ls1 += __shfl_xor_sync(0xffffffffu, ls1, 1);
        ls1 += __shfl_xor_sync(0xffffffffu, ls1, 2);
        l0 = l0 * corr0 + ls0;
        l1 = l1 * corr1 + ls1;

        #pragma unroll
        for (int nj = 0; nj < 8; nj++) {
            oacc[nj][0] *= corr0; oacc[nj][1] *= corr0;
            oacc[nj][2] *= corr1; oacc[nj][3] *= corr1;
        }

        uint32_t pa[4][4];
        #pragma unroll
        for (int kk = 0; kk < 4; kk++) {
            __half2 h0 = __floats2half2_rn(p[2 * kk][0],     p[2 * kk][1]);
            __half2 h1 = __floats2half2_rn(p[2 * kk][2],     p[2 * kk][3]);
            __half2 h2 = __floats2half2_rn(p[2 * kk + 1][0], p[2 * kk + 1][1]);
            __half2 h3 = __floats2half2_rn(p[2 * kk + 1][2], p[2 * kk + 1][3]);
            pa[kk][0] = *(uint32_t*)&h0;
            pa[kk][1] = *(uint32_t*)&h1;
            pa[kk][2] = *(uint32_t*)&h2;
            pa[kk][3] = *(uint32_t*)&h3;
        }

        uint32_t vbase = sV + (uint32_t)(((lsel & 1) * 8 + lrow) * AST) * 2
                       + (uint32_t)((lsel >> 1) * 8) * 2;
        #pragma unroll
        for (int njp = 0; njp < 4; njp++) {
            #pragma unroll
            for (int kk = 0; kk < 4; kk++) {
                uint32_t vb[4];
                LDSM4T(vb, vbase + (uint32_t)(16 * kk * AST) * 2 + (uint32_t)(16 * njp) * 2);
                MMA16816(oacc[2 * njp],     pa[kk], vb[0], vb[1]);
                MMA16816(oacc[2 * njp + 1], pa[kk], vb[2], vb[3]);
            }
        }
    }

    float inv0 = 1.f / l0, inv1 = 1.f / l1;
    int row0g = b * T + q0 + 16 * w + g;
    #pragma unroll
    for (int nj = 0; nj < 8; nj++) {
        int col = h * HD + 8 * nj + 2 * tg;
        __half2 v0 = __floats2half2_rn(oacc[nj][0] * inv0, oacc[nj][1] * inv0);
        __half2 v1 = __floats2half2_rn(oacc[nj][2] * inv1, oacc[nj][3] * inv1);
        *(__half2*)(y + (size_t)row0g * E + col) = v0;
        *(__half2*)(y + (size_t)(row0g + 8) * E + col) = v1;
    }
}

// ---------------- loss merge (reads partial LSE pairs, not logits) -----------
__global__ void loss_merge_kernel(const float* __restrict__ logits,
                                  const int* __restrict__ tgt)
{
    int row = blockIdx.x;
    int tid = threadIdx.x;
    const float* pm = g_lse_m + (size_t)row * NCB;
    const float* pl = g_lse_l + (size_t)row * NCB;
    __shared__ float rmx[8], rsm[8];

    float m = -INFINITY, l = 0.f;
    for (int i = tid; i < NCB; i += 256) {
        float mi = pm[i], li = pl[i];
        float nm = fmaxf(m, mi);
        l = l * __expf(m - nm) + li * __expf(mi - nm);
        m = nm;
    }
    #pragma unroll
    for (int o = 16; o > 0; o >>= 1) {
        float om = __shfl_xor_sync(0xffffffffu, m, o);
        float ol = __shfl_xor_sync(0xffffffffu, l, o);
        float nm = fmaxf(m, om);
        l = l * __expf(m - nm) + ol * __expf(om - nm);
        m = nm;
    }
    if ((tid & 31) == 0) { rmx[tid >> 5] = m; rsm[tid >> 5] = l; }
    __syncthreads();
    if (tid == 0) {
        float tm = rmx[0], ts = rsm[0];
        #pragma unroll
        for (int w = 1; w < 8; w++) {
            float nm = fmaxf(tm, rmx[w]);
            ts = ts * __expf(tm - nm) + rsm[w] * __expf(rmx[w] - nm);
            tm = nm;
        }
        float lse = tm + logf(ts);
        int tg = tgt[row];
        g_nll[row] = (tg != -1) ? (lse - logits[(size_t)row * V + tg]) : 0.f;
    }
}

__global__ void loss_final_kernel(const int* __restrict__ tgt,
                                  float* __restrict__ out_loss)
{
    int tid = threadIdx.x;
    float s = 0.f;
    int c = 0;
    for (int i = tid; i < BT; i += blockDim.x) {
        s += g_nll[i];
        if (tgt[i] != -1) c++;
    }
    __shared__ float sf[32];
    __shared__ int si[32];
    #pragma unroll
    for (int o = 16; o > 0; o >>= 1) {
        s += __shfl_xor_sync(0xffffffffu, s, o);
        c += __shfl_xor_sync(0xffffffffu, c, o);
    }
    if ((tid & 31) == 0) { sf[tid >> 5] = s; si[tid >> 5] = c; }
    __syncthreads();
    if (tid == 0) {
        int nw = blockDim.x >> 5;
        float ts = 0.f; int tc = 0;
        for (int w = 0; w < nw; w++) { ts += sf[w]; tc += si[w]; }
        out_loss[0] = ts / fmaxf((float)tc, 1.f);
    }
}

// ---------------- launch ----------------------------------------------------
extern "C" void kernel_launch(void* const* d_in, const int* in_sizes, int n_in,
                              void* d_out, int out_size)
{
    const int*   idx         = (const int*)d_in[0];
    const int*   targets     = (const int*)d_in[1];
    const float* wte         = (const float*)d_in[2];
    const float* wpe         = (const float*)d_in[3];
    const float* ln1_w       = (const float*)d_in[4];
    const float* ln1_b       = (const float*)d_in[5];
    const float* attn_w      = (const float*)d_in[6];
    const float* attn_proj_w = (const float*)d_in[7];
    const float* ln2_w       = (const float*)d_in[8];
    const float* ln2_b       = (const float*)d_in[9];
    const float* fc_w        = (const float*)d_in[10];
    const float* fc_proj_w   = (const float*)d_in[11];
    const float* lnf_w       = (const float*)d_in[12];
    const float* lnf_b       = (const float*)d_in[13];
    const float* lm_w        = (const float*)d_in[14];
    float* out = (float*)d_out;

    cudaFuncSetAttribute(gemm_h, cudaFuncAttributeMaxDynamicSharedMemorySize, GSMEM);

    float *gx, *glm, *gll;
    __half *ga16, *gm16, *gq16, *wqkv, *wproj, *wfc, *wfcp, *wlm;
    cudaGetSymbolAddress((void**)&gx,    g_x);
    cudaGetSymbolAddress((void**)&glm,   g_lse_m);
    cudaGetSymbolAddress((void**)&gll,   g_lse_l);
    cudaGetSymbolAddress((void**)&ga16,  g_a16);
    cudaGetSymbolAddress((void**)&gm16,  g_m16);
    cudaGetSymbolAddress((void**)&gq16,  g_q16);
    cudaGetSymbolAddress((void**)&wqkv,  g_w_qkv);
    cudaGetSymbolAddress((void**)&wproj, g_w_proj);
    cudaGetSymbolAddress((void**)&wfc,   g_w_fc);
    cudaGetSymbolAddress((void**)&wfcp,  g_w_fcp);
    cudaGetSymbolAddress((void**)&wlm,   g_w_lm);

    CvtArgs ca;
    ca.s[0] = attn_w;      ca.d[0] = wqkv;  ca.n[0] = (long)NL * 3 * E * E;
    ca.s[1] = attn_proj_w; ca.d[1] = wproj; ca.n[1] = (long)NL * E * E;
    ca.s[2] = fc_w;        ca.d[2] = wfc;   ca.n[2] = (long)NL * 4 * E * E;
    ca.s[3] = fc_proj_w;   ca.d[3] = wfcp;  ca.n[3] = (long)NL * 4 * E * E;
    ca.s[4] = lm_w;        ca.d[4] = wlm;   ca.n[4] = (long)V * E;
    cvt_all_kernel<<<dim3(256, 1, 5), 256>>>(ca);

    embed_kernel<<<BT / 8, 256>>>(idx, wte, wpe, gx);

    for (int i = 0; i < NL; i++) {
        ln_kernel<<<BT / 8, 256>>>(gx, ln1_w + (size_t)i * E, ln1_b + (size_t)i * E, ga16);
        gemm_h<<<dim3(BT / BM, 3 * E / BN), 256, GSMEM>>>(
            ga16, wqkv + (size_t)i * 3 * E * E, nullptr, gq16, nullptr, 3 * E, E, 0,
            nullptr, nullptr);
        attn_kernel<<<dim3(T / AQT, NH, B), 128>>>(gq16, ga16);
        gemm_h<<<dim3(BT / BM, E / BN), 256, GSMEM>>>(
            ga16, wproj + (size_t)i * E * E, gx, nullptr, gx, E, E, 0,
            nullptr, nullptr);
        ln_kernel<<<BT / 8, 256>>>(gx, ln2_w + (size_t)i * E, ln2_b + (size_t)i * E, ga16);
        gemm_h<<<dim3(BT / BM, 4 * E / BN), 256, GSMEM>>>(
            ga16, wfc + (size_t)i * 4 * E * E, nullptr, gm16, nullptr, 4 * E, E, 1,
            nullptr, nullptr);
        gemm_h<<<dim3(BT / BM, E / BN), 256, GSMEM>>>(
            gm16, wfcp + (size_t)i * 4 * E * E, gx, nullptr, gx, E, 4 * E, 0,
            nullptr, nullptr);
    }

    ln_kernel<<<BT / 8, 256>>>(gx, lnf_w, lnf_b, ga16);
    gemm_h<<<dim3(BT / BM, (V + BN - 1) / BN), 256, GSMEM>>>(
        ga16, wlm, out, nullptr, nullptr, V, E, 0, glm, gll);

    long long btv = (long long)BT * V;
    if ((long long)out_size > btv) {
        loss_merge_kernel<<<BT, 256>>>(out, targets);
        loss_final_kernel<<<1, 1024>>>(targets, out + btv);
    }
}